// round 6
// baseline (speedup 1.0000x reference)
#include <cuda_runtime.h>
#include <math.h>

// Problem constants (fixed by the dataset)
#define N_NODES  20000
#define N_EDGES  320000
#define N_TOT    340000      // edges + self loops
#define N_GRAPHS 512
#define H1  10
#define C1  78
#define F1  780              // H1*C1
#define C2  100
#define NEG 0.2f

// ---------------- scratch (device globals; no allocation allowed) ------------
__device__ float d_h1[N_NODES * F1];        // x @ W1
__device__ float d_as1[N_NODES * H1];
__device__ float d_ad1[N_NODES * H1];
__device__ float d_agg1[N_NODES * F1];      // elu(gat1 out)
__device__ float d_h2[N_NODES * C2];        // agg1 @ W2
__device__ float d_as2[N_NODES];
__device__ float d_ad2[N_NODES];
__device__ float d_agg2[N_NODES * C2];      // relu(gat2 out)
__device__ int   d_g[N_GRAPHS * C2];        // pooled max (float bits, vals >= 0)
__device__ int   d_cnt[N_NODES + 1];
__device__ int   d_ptr[N_NODES + 1];
__device__ int   d_cur[N_NODES];
__device__ int   d_srcs[N_TOT];             // CSR (by dst) source node ids
__device__ int   d_is64;                    // 1 if index inputs are int64

// Index accessor: works for int32 buffers and little-endian int64 buffers
// (node ids are < 2^31 and non-negative, so the low word suffices).
__device__ __forceinline__ int ld_idx(const int* __restrict__ p, int i) {
    return d_is64 ? p[2 * i] : p[i];
}

// ---------------- dtype detection --------------------------------------------
// If edge_index is int64, every odd 32-bit word is a (zero) high word.
// If int32, odd words are random node ids (P(all sampled == 0) ~ 0).
__global__ void k_detect(const int* __restrict__ ei32) {
    __shared__ int nz;
    if (threadIdx.x == 0) nz = 0;
    __syncthreads();
    // sample 256 odd words spread across the first 640000 int32 words
    // (safe to read for both layouts)
    int idx = 2 * (threadIdx.x * 1237 + 11) + 1;   // < 640000 for tid < 256
    if (ei32[idx] != 0) atomicOr(&nz, 1);
    __syncthreads();
    if (threadIdx.x == 0) d_is64 = nz ? 0 : 1;
}

// ---------------- CSR build --------------------------------------------------
__global__ void k_zero() {
    int i = blockIdx.x * blockDim.x + threadIdx.x;
    if (i <= N_NODES)       d_cnt[i] = 0;
    if (i < N_GRAPHS * C2)  d_g[i] = 0;   // bits 0 == 0.0f; pooled vals are >= 0
}

__global__ void k_count(const int* __restrict__ ei) {
    int e = blockIdx.x * blockDim.x + threadIdx.x;
    if (e >= N_TOT) return;
    int dst = (e < N_EDGES) ? ld_idx(ei, N_EDGES + e) : (e - N_EDGES);
    atomicAdd(&d_cnt[dst], 1);
}

__global__ void k_scan() {   // single block, 1024 threads, chunk=20
    __shared__ int s[1024];
    int t = threadIdx.x;
    int base = t * 20;
    int p = 0;
    #pragma unroll
    for (int i = 0; i < 20; i++) {
        int idx = base + i;
        if (idx < N_NODES) p += d_cnt[idx];
    }
    s[t] = p;
    __syncthreads();
    for (int off = 1; off < 1024; off <<= 1) {
        int add = (t >= off) ? s[t - off] : 0;
        __syncthreads();
        s[t] += add;
        __syncthreads();
    }
    int run = s[t] - p;                     // exclusive prefix
    #pragma unroll
    for (int i = 0; i < 20; i++) {
        int idx = base + i;
        if (idx < N_NODES) {
            d_ptr[idx] = run;
            d_cur[idx] = run;
            run += d_cnt[idx];
        }
    }
    if (t == 1023) d_ptr[N_NODES] = s[1023];
}

__global__ void k_scatter(const int* __restrict__ ei) {
    int e = blockIdx.x * blockDim.x + threadIdx.x;
    if (e >= N_TOT) return;
    int src, dst;
    if (e < N_EDGES) { src = ld_idx(ei, e); dst = ld_idx(ei, N_EDGES + e); }
    else             { src = dst = e - N_EDGES; }
    int pos = atomicAdd(&d_cur[dst], 1);
    d_srcs[pos] = src;
}

// ---------------- layer 1 ----------------------------------------------------
// h1 = x @ W1   (one block / node, 256 threads)
__global__ void k_gemm1(const float* __restrict__ x, const float* __restrict__ W1) {
    __shared__ float sx[C1];
    int n = blockIdx.x, t = threadIdx.x;
    if (t < C1) sx[t] = x[n * C1 + t];
    __syncthreads();
    for (int c = t; c < F1; c += 256) {
        float a = 0.f;
        #pragma unroll 6
        for (int k = 0; k < C1; k++) a += sx[k] * W1[k * F1 + c];
        d_h1[n * F1 + c] = a;
    }
}

// per-node per-head attention dots (one block / node, 10 warps)
__global__ void k_alpha1(const float* __restrict__ a_src, const float* __restrict__ a_dst) {
    int n = blockIdx.x;
    int w = threadIdx.x >> 5, lane = threadIdx.x & 31;
    float ss = 0.f, sd = 0.f;
    for (int c = lane; c < C1; c += 32) {
        float hv = d_h1[n * F1 + w * C1 + c];
        ss += hv * a_src[w * C1 + c];
        sd += hv * a_dst[w * C1 + c];
    }
    #pragma unroll
    for (int o = 16; o; o >>= 1) {
        ss += __shfl_xor_sync(0xffffffffu, ss, o);
        sd += __shfl_xor_sync(0xffffffffu, sd, o);
    }
    if (lane == 0) { d_as1[n * H1 + w] = ss; d_ad1[n * H1 + w] = sd; }
}

__device__ __forceinline__ float lrelu(float v) { return v > 0.f ? v : NEG * v; }

// GAT layer-1 aggregation + bias + elu. One block (256 thr) per dst node.
__global__ void k_agg1(const float* __restrict__ b1) {
    __shared__ float s_ad[H1];
    __shared__ float s_den[H1];
    __shared__ float s_w[32 * H1];
    __shared__ int   s_src[32];
    int n = blockIdx.x, t = threadIdx.x;
    int lane = t & 31, warp = t >> 5;
    int beg = d_ptr[n], end = d_ptr[n + 1];
    if (t < H1) s_ad[t] = d_ad1[n * H1 + t];
    __syncthreads();

    // pass 1: per-head max over incoming edges (warp 0)
    float m[H1];
    if (warp == 0) {
        #pragma unroll
        for (int h = 0; h < H1; h++) m[h] = -INFINITY;
        for (int e = beg + lane; e < end; e += 32) {
            int s = d_srcs[e];
            #pragma unroll
            for (int h = 0; h < H1; h++)
                m[h] = fmaxf(m[h], lrelu(d_as1[s * H1 + h] + s_ad[h]));
        }
        #pragma unroll
        for (int h = 0; h < H1; h++) {
            float v = m[h];
            #pragma unroll
            for (int o = 16; o; o >>= 1) v = fmaxf(v, __shfl_xor_sync(0xffffffffu, v, o));
            m[h] = v;   // all lanes hold the max
        }
    }

    // this thread's channels: t, t+256, t+512, (t+768 if t<12)
    int c0 = t, c1 = t + 256, c2 = t + 512, c3 = t + 768;
    int h0 = c0 / C1, hh1 = c1 / C1, hh2 = c2 / C1;
    bool has3 = (c3 < F1);
    int h3 = has3 ? (c3 / C1) : 0;
    float a0 = 0.f, a1 = 0.f, a2 = 0.f, a3 = 0.f;
    float ld[H1];
    if (warp == 0) {
        #pragma unroll
        for (int h = 0; h < H1; h++) ld[h] = 0.f;
    }

    // pass 2: chunked exp-weights + weighted gather-accumulate
    for (int base = beg; base < end; base += 32) {
        __syncthreads();
        if (warp == 0) {
            int e = base + lane;
            if (e < end) {
                int s = d_srcs[e];
                s_src[lane] = s;
                #pragma unroll
                for (int h = 0; h < H1; h++) {
                    float w = expf(lrelu(d_as1[s * H1 + h] + s_ad[h]) - m[h]);
                    s_w[lane * H1 + h] = w;
                    ld[h] += w;
                }
            }
        }
        __syncthreads();
        int nl = min(32, end - base);
        for (int e = 0; e < nl; e++) {
            const float* hr = d_h1 + (long)s_src[e] * F1;
            const float* wr = s_w + e * H1;
            a0 += wr[h0] * hr[c0];
            a1 += wr[hh1] * hr[c1];
            a2 += wr[hh2] * hr[c2];
            if (has3) a3 += wr[h3] * hr[c3];
        }
    }
    if (warp == 0) {
        #pragma unroll
        for (int h = 0; h < H1; h++) {
            float v = ld[h];
            #pragma unroll
            for (int o = 16; o; o >>= 1) v += __shfl_xor_sync(0xffffffffu, v, o);
            if (lane == 0) s_den[h] = v;
        }
    }
    __syncthreads();

    float v0 = a0 / (s_den[h0] + 1e-16f) + b1[c0];
    float v1 = a1 / (s_den[hh1] + 1e-16f) + b1[c1];
    float v2 = a2 / (s_den[hh2] + 1e-16f) + b1[c2];
    d_agg1[n * F1 + c0] = v0 > 0.f ? v0 : expm1f(v0);
    d_agg1[n * F1 + c1] = v1 > 0.f ? v1 : expm1f(v1);
    d_agg1[n * F1 + c2] = v2 > 0.f ? v2 : expm1f(v2);
    if (has3) {
        float v3 = a3 / (s_den[h3] + 1e-16f) + b1[c3];
        d_agg1[n * F1 + c3] = v3 > 0.f ? v3 : expm1f(v3);
    }
}

// ---------------- layer 2 ----------------------------------------------------
// h2 = agg1 @ W2   (one block / node, 128 threads; 100 active)
__global__ void k_gemm2(const float* __restrict__ W2) {
    __shared__ float sr[F1];
    int n = blockIdx.x, t = threadIdx.x;
    for (int k = t; k < F1; k += 128) sr[k] = d_agg1[n * F1 + k];
    __syncthreads();
    if (t < C2) {
        float a = 0.f;
        #pragma unroll 4
        for (int k = 0; k < F1; k++) a += sr[k] * W2[k * C2 + t];
        d_h2[n * C2 + t] = a;
    }
}

__global__ void k_alpha2(const float* __restrict__ a_src, const float* __restrict__ a_dst) {
    int node = blockIdx.x * (blockDim.x >> 5) + (threadIdx.x >> 5);
    int lane = threadIdx.x & 31;
    if (node >= N_NODES) return;
    float ss = 0.f, sd = 0.f;
    for (int c = lane; c < C2; c += 32) {
        float hv = d_h2[node * C2 + c];
        ss += hv * a_src[c];
        sd += hv * a_dst[c];
    }
    #pragma unroll
    for (int o = 16; o; o >>= 1) {
        ss += __shfl_xor_sync(0xffffffffu, ss, o);
        sd += __shfl_xor_sync(0xffffffffu, sd, o);
    }
    if (lane == 0) { d_as2[node] = ss; d_ad2[node] = sd; }
}

// GAT layer-2 aggregation + bias + relu. One block (128 thr) per dst node.
__global__ void k_agg2(const float* __restrict__ b2) {
    __shared__ float s_w[32];
    __shared__ int   s_src[32];
    __shared__ float s_den;
    int n = blockIdx.x, t = threadIdx.x;
    int lane = t & 31, warp = t >> 5;
    int beg = d_ptr[n], end = d_ptr[n + 1];
    float ad = d_ad2[n];

    float m = -INFINITY;
    if (warp == 0) {
        for (int e = beg + lane; e < end; e += 32)
            m = fmaxf(m, lrelu(d_as2[d_srcs[e]] + ad));
        #pragma unroll
        for (int o = 16; o; o >>= 1) m = fmaxf(m, __shfl_xor_sync(0xffffffffu, m, o));
    }

    float acc = 0.f, ldn = 0.f;
    for (int base = beg; base < end; base += 32) {
        __syncthreads();
        if (warp == 0) {
            int e = base + lane;
            if (e < end) {
                int s = d_srcs[e];
                s_src[lane] = s;
                float w = expf(lrelu(d_as2[s] + ad) - m);
                s_w[lane] = w;
                ldn += w;
            }
        }
        __syncthreads();
        int nl = min(32, end - base);
        if (t < C2) {
            for (int e = 0; e < nl; e++)
                acc += s_w[e] * d_h2[s_src[e] * C2 + t];
        }
    }
    if (warp == 0) {
        #pragma unroll
        for (int o = 16; o; o >>= 1) ldn += __shfl_xor_sync(0xffffffffu, ldn, o);
        if (lane == 0) s_den = ldn;
    }
    __syncthreads();
    if (t < C2) {
        float v = acc / (s_den + 1e-16f) + b2[t];
        d_agg2[n * C2 + t] = fmaxf(v, 0.f);
    }
}

// ---------------- pooling + head ---------------------------------------------
__global__ void k_pool(const int* __restrict__ batch) {
    int i = blockIdx.x * blockDim.x + threadIdx.x;
    if (i >= N_NODES * C2) return;
    int n = i / C2, c = i - n * C2;
    int b = ld_idx(batch, n);
    // values are relu'd (>= 0): int bit pattern is order-preserving
    atomicMax(&d_g[b * C2 + c], __float_as_int(d_agg2[i]));
}

__global__ void k_final(const float* __restrict__ Wg, const float* __restrict__ bg,
                        float* __restrict__ out) {
    __shared__ float sg[C2];
    int g = blockIdx.x, t = threadIdx.x;
    if (t < C2) sg[t] = __int_as_float(d_g[g * C2 + t]);
    __syncthreads();
    if (t < C2) {
        float a = bg[t];
        #pragma unroll 4
        for (int k = 0; k < C2; k++) a += sg[k] * Wg[k * C2 + t];
        out[g * C2 + t] = fmaxf(a, 0.f);
    }
}

// ---------------- launch ------------------------------------------------------
extern "C" void kernel_launch(void* const* d_in, const int* in_sizes, int n_in,
                              void* d_out, int out_size) {
    const float* x     = (const float*)d_in[0];
    const int*   ei    = (const int*)d_in[1];     // int32 or int64 (detected on device)
    const int*   batch = (const int*)d_in[2];

    // Robustly locate W1 (60840 elements): the scalar num_graphs input may or
    // may not be materialized as a device buffer.
    int base = 3;
    while (base < n_in && in_sizes[base] != 78 * F1) base++;
    if (base >= n_in) base = (n_in >= 14) ? 4 : 3;

    const float* W1     = (const float*)d_in[base + 0];
    const float* a_src1 = (const float*)d_in[base + 1];
    const float* a_dst1 = (const float*)d_in[base + 2];
    const float* b1     = (const float*)d_in[base + 3];
    const float* W2     = (const float*)d_in[base + 4];
    const float* a_src2 = (const float*)d_in[base + 5];
    const float* a_dst2 = (const float*)d_in[base + 6];
    const float* b2     = (const float*)d_in[base + 7];
    const float* Wg     = (const float*)d_in[base + 8];
    const float* bg     = (const float*)d_in[base + 9];
    float* out = (float*)d_out;

    k_detect<<<1, 256>>>(ei);
    k_zero<<<(N_GRAPHS * C2 + 255) / 256, 256>>>();
    k_count<<<(N_TOT + 255) / 256, 256>>>(ei);
    k_scan<<<1, 1024>>>();
    k_scatter<<<(N_TOT + 255) / 256, 256>>>(ei);

    k_gemm1<<<N_NODES, 256>>>(x, W1);
    k_alpha1<<<N_NODES, 320>>>(a_src1, a_dst1);
    k_agg1<<<N_NODES, 256>>>(b1);

    k_gemm2<<<N_NODES, 128>>>(W2);
    k_alpha2<<<(N_NODES + 7) / 8, 256>>>(a_src2, a_dst2);
    k_agg2<<<N_NODES, 128>>>(b2);

    k_pool<<<(N_NODES * C2 + 255) / 256, 256>>>(batch);
    k_final<<<N_GRAPHS, 128>>>(Wg, bg, out);
}

// round 7
// speedup vs baseline: 1.7342x; 1.7342x over previous
#include <cuda_runtime.h>
#include <math.h>

// Problem constants (fixed by the dataset)
#define N_NODES  20000
#define N_EDGES  320000
#define N_TOT    340000      // edges + self loops
#define N_GRAPHS 512
#define H1  10
#define C1  78
#define F1  780              // H1*C1
#define C2  100
#define NEG 0.2f

// ---------------- scratch (device globals; no allocation allowed) ------------
__device__ float d_h1[N_NODES * F1];        // x @ W1
__device__ float d_as1[N_NODES * H1];
__device__ float d_ad1[N_NODES * H1];
__device__ float d_agg1[N_NODES * F1];      // elu(gat1 out)
__device__ float d_h2[N_NODES * C2];        // agg1 @ W2
__device__ float d_as2[N_NODES];
__device__ float d_ad2[N_NODES];
__device__ int   d_g[N_GRAPHS * C2];        // pooled max (float bits, vals >= 0)
__device__ int   d_cnt[N_NODES + 1];
__device__ int   d_ptr[N_NODES + 1];
__device__ int   d_cur[N_NODES];
__device__ int   d_srcs[N_TOT];             // CSR (by dst) source node ids
__device__ int   d_is64;                    // 1 if index inputs are int64

// Index accessor: works for int32 buffers and little-endian int64 buffers
__device__ __forceinline__ int ld_idx(const int* __restrict__ p, int i) {
    return d_is64 ? p[2 * i] : p[i];
}

__device__ __forceinline__ float lrelu(float v) { return v > 0.f ? v : NEG * v; }

// ---------------- dtype detection --------------------------------------------
__global__ void k_detect(const int* __restrict__ ei32) {
    __shared__ int nz;
    if (threadIdx.x == 0) nz = 0;
    __syncthreads();
    int idx = 2 * (threadIdx.x * 1237 + 11) + 1;
    if (ei32[idx] != 0) atomicOr(&nz, 1);
    __syncthreads();
    if (threadIdx.x == 0) d_is64 = nz ? 0 : 1;
}

// ---------------- CSR build --------------------------------------------------
__global__ void k_zero() {
    int i = blockIdx.x * blockDim.x + threadIdx.x;
    if (i <= N_NODES)       d_cnt[i] = 0;
    if (i < N_GRAPHS * C2)  d_g[i] = 0;
}

__global__ void k_count(const int* __restrict__ ei) {
    int e = blockIdx.x * blockDim.x + threadIdx.x;
    if (e >= N_TOT) return;
    int dst = (e < N_EDGES) ? ld_idx(ei, N_EDGES + e) : (e - N_EDGES);
    atomicAdd(&d_cnt[dst], 1);
}

// warp-shuffle scan: 1024 threads, 20 elems each, 2 barriers
__global__ void k_scan() {
    __shared__ int warpsum[32];
    int t = threadIdx.x;
    int lane = t & 31, wp = t >> 5;
    int base = t * 20;
    int loc[20];
    int p = 0;
    #pragma unroll
    for (int i = 0; i < 20; i++) {
        int idx = base + i;
        int v = (idx < N_NODES) ? d_cnt[idx] : 0;
        loc[i] = p;
        p += v;
    }
    int inc = p;
    #pragma unroll
    for (int o = 1; o < 32; o <<= 1) {
        int v = __shfl_up_sync(0xffffffffu, inc, o);
        if (lane >= o) inc += v;
    }
    if (lane == 31) warpsum[wp] = inc;
    __syncthreads();
    if (wp == 0) {
        int v = warpsum[lane];
        int iv = v;
        #pragma unroll
        for (int o = 1; o < 32; o <<= 1) {
            int u = __shfl_up_sync(0xffffffffu, iv, o);
            if (lane >= o) iv += u;
        }
        warpsum[lane] = iv - v;   // exclusive warp offsets
    }
    __syncthreads();
    int off = warpsum[wp] + (inc - p);
    #pragma unroll
    for (int i = 0; i < 20; i++) {
        int idx = base + i;
        if (idx < N_NODES) {
            int val = off + loc[i];
            d_ptr[idx] = val;
            d_cur[idx] = val;
        }
    }
    if (t == 1023) d_ptr[N_NODES] = warpsum[31] + inc;
}

__global__ void k_scatter(const int* __restrict__ ei) {
    int e = blockIdx.x * blockDim.x + threadIdx.x;
    if (e >= N_TOT) return;
    int src, dst;
    if (e < N_EDGES) { src = ld_idx(ei, e); dst = ld_idx(ei, N_EDGES + e); }
    else             { src = dst = e - N_EDGES; }
    int pos = atomicAdd(&d_cur[dst], 1);
    d_srcs[pos] = src;
}

// ---------------- layer 1: tiled GEMM + fused alpha dots ---------------------
// grid (ceil(N/64), 10 heads), block 256 (16x16), thread tile 4x5
__global__ void k_gemm1(const float* __restrict__ x, const float* __restrict__ W1,
                        const float* __restrict__ a_src1, const float* __restrict__ a_dst1) {
    __shared__ float sx[64][81];
    __shared__ float sw[78][80];
    __shared__ float sds[64][2];
    int g  = blockIdx.y;
    int n0 = blockIdx.x * 64;
    int t  = threadIdx.x;
    int tx = t & 15, ty = t >> 4;

    for (int idx = t; idx < 64 * 78; idx += 256) {
        int r = idx / 78, c = idx - r * 78;
        int node = n0 + r;
        sx[r][c] = (node < N_NODES) ? x[node * 78 + c] : 0.f;
    }
    for (int idx = t; idx < 78 * 80; idx += 256) {
        int k = idx / 80, c = idx - k * 80;
        sw[k][c] = (c < 78) ? W1[k * F1 + g * 78 + c] : 0.f;
    }
    if (t < 64) { sds[t][0] = 0.f; sds[t][1] = 0.f; }
    __syncthreads();

    float acc[4][5];
    #pragma unroll
    for (int i = 0; i < 4; i++)
        #pragma unroll
        for (int j = 0; j < 5; j++) acc[i][j] = 0.f;
    int mb = ty * 4, nb = tx * 5;
    #pragma unroll 6
    for (int k = 0; k < 78; k++) {
        float a[4], b[5];
        #pragma unroll
        for (int i = 0; i < 4; i++) a[i] = sx[mb + i][k];
        #pragma unroll
        for (int j = 0; j < 5; j++) b[j] = sw[k][nb + j];
        #pragma unroll
        for (int i = 0; i < 4; i++)
            #pragma unroll
            for (int j = 0; j < 5; j++) acc[i][j] += a[i] * b[j];
    }

    // fused alpha partial dots
    float asr[5], adr[5];
    #pragma unroll
    for (int j = 0; j < 5; j++) {
        int nn = nb + j;
        asr[j] = (nn < 78) ? a_src1[g * 78 + nn] : 0.f;
        adr[j] = (nn < 78) ? a_dst1[g * 78 + nn] : 0.f;
    }
    #pragma unroll
    for (int i = 0; i < 4; i++) {
        float ps = 0.f, pd = 0.f;
        #pragma unroll
        for (int j = 0; j < 5; j++) { ps += acc[i][j] * asr[j]; pd += acc[i][j] * adr[j]; }
        atomicAdd(&sds[mb + i][0], ps);
        atomicAdd(&sds[mb + i][1], pd);
    }

    #pragma unroll
    for (int i = 0; i < 4; i++) {
        int node = n0 + mb + i;
        if (node < N_NODES) {
            #pragma unroll
            for (int j = 0; j < 5; j++) {
                int nn = nb + j;
                if (nn < 78) d_h1[(size_t)node * F1 + g * 78 + nn] = acc[i][j];
            }
        }
    }
    __syncthreads();
    if (t < 64) {
        int node = n0 + t;
        if (node < N_NODES) {
            d_as1[node * H1 + g] = sds[t][0];
            d_ad1[node * H1 + g] = sds[t][1];
        }
    }
}

// GAT layer-1 aggregation + bias + elu. One block (256 thr) per dst node.
__global__ void k_agg1(const float* __restrict__ b1) {
    __shared__ float s_ad[H1], s_m[H1], s_ld[H1];
    __shared__ float s_pm[8][H1];
    __shared__ float s_w[64 * H1];
    __shared__ int   s_src[64];
    int n = blockIdx.x, t = threadIdx.x;
    int lane = t & 31, wp = t >> 5;
    int beg = d_ptr[n], end = d_ptr[n + 1];
    if (t < H1) { s_ad[t] = d_ad1[n * H1 + t]; s_ld[t] = 0.f; }
    __syncthreads();

    // pass 1: per-head max over incoming edges (all 8 warps)
    float m[H1];
    #pragma unroll
    for (int h = 0; h < H1; h++) m[h] = -INFINITY;
    for (int e = beg + t; e < end; e += 256) {
        int s = d_srcs[e];
        const float* as = d_as1 + s * H1;
        #pragma unroll
        for (int h = 0; h < H1; h++)
            m[h] = fmaxf(m[h], lrelu(as[h] + s_ad[h]));
    }
    #pragma unroll
    for (int h = 0; h < H1; h++) {
        float v = m[h];
        #pragma unroll
        for (int o = 16; o; o >>= 1) v = fmaxf(v, __shfl_xor_sync(0xffffffffu, v, o));
        if (lane == 0) s_pm[wp][h] = v;
    }
    __syncthreads();
    if (t < H1) {
        float v = s_pm[0][t];
        #pragma unroll
        for (int w = 1; w < 8; w++) v = fmaxf(v, s_pm[w][t]);
        s_m[t] = v;
    }

    // gather setup: thread t handles channels 4t..4t+3 (t < 195)
    int c4 = 4 * t;
    int hlo = c4 / C1, hhi = (c4 + 3) / C1;
    bool s1 = ((c4 + 1) / C1) == hlo;
    bool s2 = ((c4 + 2) / C1) == hlo;
    float a0 = 0.f, a1 = 0.f, a2 = 0.f, a3 = 0.f;

    for (int base = beg; base < end; base += 64) {
        int nl = min(64, end - base);
        __syncthreads();   // also orders s_m init before first use
        for (int item = t; item < nl * H1; item += 256) {
            int el = item / H1, h = item - el * H1;
            int s = d_srcs[base + el];
            if (h == 0) s_src[el] = s;
            float w = expf(lrelu(d_as1[s * H1 + h] + s_ad[h]) - s_m[h]);
            s_w[item] = w;
            atomicAdd(&s_ld[h], w);
        }
        __syncthreads();
        if (t < 195) {
            #pragma unroll 4
            for (int el = 0; el < nl; el++) {
                float4 v = *(const float4*)(d_h1 + (size_t)s_src[el] * F1 + c4);
                const float* wr = s_w + el * H1;
                float wlo = wr[hlo], whi = wr[hhi];
                a0 += v.x * wlo;
                a1 += v.y * (s1 ? wlo : whi);
                a2 += v.z * (s2 ? wlo : whi);
                a3 += v.w * whi;
            }
        }
    }
    __syncthreads();
    if (t < 195) {
        float dlo = s_ld[hlo] + 1e-16f, dhi = s_ld[hhi] + 1e-16f;
        float4 o;
        o.x = a0 / dlo + b1[c4];
        o.y = a1 / (s1 ? dlo : dhi) + b1[c4 + 1];
        o.z = a2 / (s2 ? dlo : dhi) + b1[c4 + 2];
        o.w = a3 / dhi + b1[c4 + 3];
        o.x = o.x > 0.f ? o.x : expm1f(o.x);
        o.y = o.y > 0.f ? o.y : expm1f(o.y);
        o.z = o.z > 0.f ? o.z : expm1f(o.z);
        o.w = o.w > 0.f ? o.w : expm1f(o.w);
        *(float4*)(d_agg1 + (size_t)n * F1 + c4) = o;
    }
}

// ---------------- layer 2: tiled GEMM + fused alpha dots ---------------------
// grid ceil(N/64), block 256 (16x16), thread tile 4x7, K tiles of 60
__global__ void k_gemm2(const float* __restrict__ W2,
                        const float* __restrict__ a_src2, const float* __restrict__ a_dst2) {
    __shared__ float sa[64][61];
    __shared__ float sw[60][112];
    __shared__ float sds[64][2];
    int n0 = blockIdx.x * 64;
    int t = threadIdx.x, tx = t & 15, ty = t >> 4;
    int mb = ty * 4, nb = tx * 7;

    float acc[4][7];
    #pragma unroll
    for (int i = 0; i < 4; i++)
        #pragma unroll
        for (int j = 0; j < 7; j++) acc[i][j] = 0.f;
    if (t < 64) { sds[t][0] = 0.f; sds[t][1] = 0.f; }

    for (int k0 = 0; k0 < F1; k0 += 60) {
        __syncthreads();
        for (int idx = t; idx < 64 * 60; idx += 256) {
            int r = idx / 60, c = idx - r * 60;
            int node = n0 + r;
            sa[r][c] = (node < N_NODES) ? d_agg1[(size_t)node * F1 + k0 + c] : 0.f;
        }
        for (int idx = t; idx < 60 * 112; idx += 256) {
            int k = idx / 112, c = idx - k * 112;
            sw[k][c] = (c < C2) ? W2[(k0 + k) * C2 + c] : 0.f;
        }
        __syncthreads();
        #pragma unroll 4
        for (int kk = 0; kk < 60; kk++) {
            float a[4], b[7];
            #pragma unroll
            for (int i = 0; i < 4; i++) a[i] = sa[mb + i][kk];
            #pragma unroll
            for (int j = 0; j < 7; j++) b[j] = sw[kk][nb + j];
            #pragma unroll
            for (int i = 0; i < 4; i++)
                #pragma unroll
                for (int j = 0; j < 7; j++) acc[i][j] += a[i] * b[j];
        }
    }

    float asr[7], adr[7];
    #pragma unroll
    for (int j = 0; j < 7; j++) {
        int nn = nb + j;
        asr[j] = (nn < C2) ? a_src2[nn] : 0.f;
        adr[j] = (nn < C2) ? a_dst2[nn] : 0.f;
    }
    #pragma unroll
    for (int i = 0; i < 4; i++) {
        float ps = 0.f, pd = 0.f;
        #pragma unroll
        for (int j = 0; j < 7; j++) { ps += acc[i][j] * asr[j]; pd += acc[i][j] * adr[j]; }
        atomicAdd(&sds[mb + i][0], ps);
        atomicAdd(&sds[mb + i][1], pd);
    }
    #pragma unroll
    for (int i = 0; i < 4; i++) {
        int node = n0 + mb + i;
        if (node < N_NODES) {
            #pragma unroll
            for (int j = 0; j < 7; j++) {
                int nn = nb + j;
                if (nn < C2) d_h2[(size_t)node * C2 + nn] = acc[i][j];
            }
        }
    }
    __syncthreads();
    if (t < 64) {
        int node = n0 + t;
        if (node < N_NODES) {
            d_as2[node] = sds[t][0];
            d_ad2[node] = sds[t][1];
        }
    }
}

// GAT layer-2 aggregation + bias + relu + fused global max pool.
// One block (128 thr) per dst node.
__global__ void k_agg2(const float* __restrict__ b2, const int* __restrict__ batch) {
    __shared__ float s_w[64];
    __shared__ int   s_src[64];
    __shared__ float s_red[4];
    __shared__ float s_m1, s_den;
    int n = blockIdx.x, t = threadIdx.x;
    int lane = t & 31, wp = t >> 5;
    int beg = d_ptr[n], end = d_ptr[n + 1];
    float ad = d_ad2[n];

    float m = -INFINITY;
    for (int e = beg + t; e < end; e += 128)
        m = fmaxf(m, lrelu(d_as2[d_srcs[e]] + ad));
    #pragma unroll
    for (int o = 16; o; o >>= 1) m = fmaxf(m, __shfl_xor_sync(0xffffffffu, m, o));
    if (lane == 0) s_red[wp] = m;
    __syncthreads();
    if (t == 0) {
        s_m1 = fmaxf(fmaxf(s_red[0], s_red[1]), fmaxf(s_red[2], s_red[3]));
        s_den = 0.f;
    }

    float acc = 0.f;
    for (int base = beg; base < end; base += 64) {
        int nl = min(64, end - base);
        __syncthreads();
        if (t < nl) {
            int s = d_srcs[base + t];
            s_src[t] = s;
            float w = expf(lrelu(d_as2[s] + ad) - s_m1);
            s_w[t] = w;
            atomicAdd(&s_den, w);
        }
        __syncthreads();
        if (t < C2) {
            #pragma unroll 4
            for (int el = 0; el < nl; el++)
                acc += s_w[el] * d_h2[(size_t)s_src[el] * C2 + t];
        }
    }
    __syncthreads();
    if (t < C2) {
        float v = acc / (s_den + 1e-16f) + b2[t];
        v = fmaxf(v, 0.f);
        int b = ld_idx(batch, n);
        atomicMax(&d_g[b * C2 + t], __float_as_int(v));
    }
}

// ---------------- head -------------------------------------------------------
__global__ void k_final(const float* __restrict__ Wg, const float* __restrict__ bg,
                        float* __restrict__ out) {
    __shared__ float sg[C2];
    int g = blockIdx.x, t = threadIdx.x;
    if (t < C2) sg[t] = __int_as_float(d_g[g * C2 + t]);
    __syncthreads();
    if (t < C2) {
        float a = bg[t];
        #pragma unroll 4
        for (int k = 0; k < C2; k++) a += sg[k] * Wg[k * C2 + t];
        out[g * C2 + t] = fmaxf(a, 0.f);
    }
}

// ---------------- launch ------------------------------------------------------
extern "C" void kernel_launch(void* const* d_in, const int* in_sizes, int n_in,
                              void* d_out, int out_size) {
    const float* x     = (const float*)d_in[0];
    const int*   ei    = (const int*)d_in[1];     // int32 or int64 (device-detected)
    const int*   batch = (const int*)d_in[2];

    int base = 3;
    while (base < n_in && in_sizes[base] != 78 * F1) base++;
    if (base >= n_in) base = (n_in >= 14) ? 4 : 3;

    const float* W1     = (const float*)d_in[base + 0];
    const float* a_src1 = (const float*)d_in[base + 1];
    const float* a_dst1 = (const float*)d_in[base + 2];
    const float* b1     = (const float*)d_in[base + 3];
    const float* W2     = (const float*)d_in[base + 4];
    const float* a_src2 = (const float*)d_in[base + 5];
    const float* a_dst2 = (const float*)d_in[base + 6];
    const float* b2     = (const float*)d_in[base + 7];
    const float* Wg     = (const float*)d_in[base + 8];
    const float* bg     = (const float*)d_in[base + 9];
    float* out = (float*)d_out;

    k_detect<<<1, 256>>>(ei);
    k_zero<<<(N_GRAPHS * C2 + 255) / 256, 256>>>();
    k_count<<<(N_TOT + 255) / 256, 256>>>(ei);
    k_scan<<<1, 1024>>>();
    k_scatter<<<(N_TOT + 255) / 256, 256>>>(ei);

    dim3 g1((N_NODES + 63) / 64, H1);
    k_gemm1<<<g1, 256>>>(x, W1, a_src1, a_dst1);
    k_agg1<<<N_NODES, 256>>>(b1);

    k_gemm2<<<(N_NODES + 63) / 64, 256>>>(W2, a_src2, a_dst2);
    k_agg2<<<N_NODES, 128>>>(b2, batch);

    k_final<<<N_GRAPHS, 128>>>(Wg, bg, out);
}